// round 2
// baseline (speedup 1.0000x reference)
#include <cuda_runtime.h>

// IFOPooling: h_t = f_t * h_{t-1} + i_t * z_t over contiguous S axis.
// f,z,i: [B,H,S] fp32 (B=16,H=1024,S=2048). out: [B,H,S] fp32.
//
// Persistent blocks, one row (2048 elems) per iteration, 256 threads x 8 elems.
// Software pipeline: next row's loads issued before current row's scan, so
// DRAM fetch overlaps the barrier + shuffle-scan phase.

#define SEQ_LEN 2048
#define TPB 256
#define EPT 8
#define NWARPS (TPB / 32)
#define GRID 592          // 148 SMs * 4 resident CTAs

__global__ __launch_bounds__(TPB, 4) void ifo_scan_kernel(
    const float* __restrict__ f,
    const float* __restrict__ z,
    const float* __restrict__ in_i,
    float* __restrict__ out,
    int rows)
{
    __shared__ float wa[2][NWARPS];
    __shared__ float wb[2][NWARPS];

    const int t    = threadIdx.x;
    const int lane = t & 31;
    const int wid  = t >> 5;
    const unsigned mask = 0xffffffffu;

    int row = blockIdx.x;
    if (row >= rows) return;               // uniform per block

    const int stride = gridDim.x;
    const size_t toff = (size_t)t * EPT;

    // ---- prologue: load first row ----
    size_t off = (size_t)row * SEQ_LEN + toff;
    float4 cf0 = *(const float4*)(f    + off);
    float4 cf1 = *(const float4*)(f    + off + 4);
    float4 cz0 = *(const float4*)(z    + off);
    float4 cz1 = *(const float4*)(z    + off + 4);
    float4 ci0 = *(const float4*)(in_i + off);
    float4 ci1 = *(const float4*)(in_i + off + 4);

    int parity = 0;

    for (;;) {
        // ---- issue next row's loads FIRST (overlap with scan below) ----
        const int next = row + stride;
        const bool has_next = next < rows;
        float4 nf0, nf1, nz0, nz1, ni0, ni1;
        if (has_next) {
            size_t noff = (size_t)next * SEQ_LEN + toff;
            nf0 = *(const float4*)(f    + noff);
            nf1 = *(const float4*)(f    + noff + 4);
            nz0 = *(const float4*)(z    + noff);
            nz1 = *(const float4*)(z    + noff + 4);
            ni0 = *(const float4*)(in_i + noff);
            ni1 = *(const float4*)(in_i + noff + 4);
        }

        // ---- current row: local values ----
        float fv[EPT] = {cf0.x, cf0.y, cf0.z, cf0.w, cf1.x, cf1.y, cf1.z, cf1.w};
        float xv[EPT] = {ci0.x * cz0.x, ci0.y * cz0.y, ci0.z * cz0.z, ci0.w * cz0.w,
                         ci1.x * cz1.x, ci1.y * cz1.y, ci1.z * cz1.z, ci1.w * cz1.w};

        // ---- thread-local composition: h -> a*h + b over 8 elements ----
        float a = 1.0f, b = 0.0f;
#pragma unroll
        for (int k = 0; k < EPT; k++) {
            a = fv[k] * a;
            b = fmaf(fv[k], b, xv[k]);
        }

        // ---- warp-inclusive scan of (a,b) ----
        float ia = a, ib = b;
#pragma unroll
        for (int d = 1; d < 32; d <<= 1) {
            float pa = __shfl_up_sync(mask, ia, d);
            float pb = __shfl_up_sync(mask, ib, d);
            if (lane >= d) {
                ib = fmaf(ia, pb, ib);
                ia = ia * pa;
            }
        }
        // exclusive within warp
        float ea = __shfl_up_sync(mask, ia, 1);
        float eb = __shfl_up_sync(mask, ib, 1);
        if (lane == 0) { ea = 1.0f; eb = 0.0f; }

        // ---- publish warp aggregates; ONE barrier per row ----
        if (lane == 31) { wa[parity][wid] = ia; wb[parity][wid] = ib; }
        __syncthreads();

        // ---- redundant per-thread exclusive scan over warp aggregates ----
        // (broadcast LDS reads, no second barrier; parity buffers make the
        //  next row's writes WAR-safe past this row's single barrier)
        float pa = 1.0f, pb = 0.0f;
#pragma unroll
        for (int w = 0; w < NWARPS - 1; w++) {
            if (w < wid) {
                pb = fmaf(wa[parity][w], pb, wb[parity][w]);
                pa = wa[parity][w] * pa;
            }
        }

        // h entering this thread's segment (h_{-1}=0 => warp-start h = pb)
        float h = fmaf(ea, pb, eb);

        // ---- replay local recurrence with true prefix ----
#pragma unroll
        for (int k = 0; k < EPT; k++) {
            h = fmaf(fv[k], h, xv[k]);
            xv[k] = h;
        }

        // ---- vectorized stores ----
        *(float4*)(out + off)     = make_float4(xv[0], xv[1], xv[2], xv[3]);
        *(float4*)(out + off + 4) = make_float4(xv[4], xv[5], xv[6], xv[7]);

        if (!has_next) break;

        // ---- rotate pipeline ----
        cf0 = nf0; cf1 = nf1;
        cz0 = nz0; cz1 = nz1;
        ci0 = ni0; ci1 = ni1;
        row = next;
        off = (size_t)row * SEQ_LEN + toff;
        parity ^= 1;
    }
}

extern "C" void kernel_launch(void* const* d_in, const int* in_sizes, int n_in,
                              void* d_out, int out_size)
{
    const float* f  = (const float*)d_in[0];
    const float* z  = (const float*)d_in[1];
    const float* ii = (const float*)d_in[2];
    float* out = (float*)d_out;

    const int rows = out_size / SEQ_LEN;   // B*H = 16384
    int grid = GRID < rows ? GRID : rows;
    ifo_scan_kernel<<<grid, TPB>>>(f, z, ii, out, rows);
}

// round 5
// speedup vs baseline: 1.0215x; 1.0215x over previous
#include <cuda_runtime.h>

// IFOPooling: h_t = f_t * h_{t-1} + i_t * z_t over the contiguous S axis.
// f,z,i: [B,H,S] fp32 (B=16,H=1024,S=2048). out: [B,H,S] fp32.
//
// One 256-thread block per row, 8 elems/thread. Linear-recurrence scan via
// composition (a,b): h -> a*h + b. Single barrier per row: warp aggregates
// published to smem, then every thread redundantly computes its warp-prefix
// (broadcast LDS reads) instead of a serialized scan + second barrier.

#define SEQ_LEN 2048
#define TPB 256
#define EPT 8
#define NWARPS (TPB / 32)

__global__ __launch_bounds__(TPB, 8) void ifo_scan_kernel(
    const float* __restrict__ f,
    const float* __restrict__ z,
    const float* __restrict__ in_i,
    float* __restrict__ out)
{
    __shared__ float wa[NWARPS];
    __shared__ float wb[NWARPS];

    const size_t base = (size_t)blockIdx.x * SEQ_LEN;
    const int t    = threadIdx.x;
    const int lane = t & 31;
    const int wid  = t >> 5;
    const size_t off = base + (size_t)t * EPT;
    const unsigned mask = 0xffffffffu;

    // ---- vectorized streaming loads (evict-first: data touched once) ----
    const float4 fA = __ldcs((const float4*)(f    + off));
    const float4 fB = __ldcs((const float4*)(f    + off + 4));
    const float4 zA = __ldcs((const float4*)(z    + off));
    const float4 zB = __ldcs((const float4*)(z    + off + 4));
    const float4 iA = __ldcs((const float4*)(in_i + off));
    const float4 iB = __ldcs((const float4*)(in_i + off + 4));

    float fv[EPT] = {fA.x, fA.y, fA.z, fA.w, fB.x, fB.y, fB.z, fB.w};
    float xv[EPT] = {iA.x * zA.x, iA.y * zA.y, iA.z * zA.z, iA.w * zA.w,
                     iB.x * zB.x, iB.y * zB.y, iB.z * zB.z, iB.w * zB.w};

    // ---- thread-local composition over 8 elements: h -> a*h + b ----
    float a = 1.0f, b = 0.0f;
#pragma unroll
    for (int k = 0; k < EPT; k++) {
        a = fv[k] * a;
        b = fmaf(fv[k], b, xv[k]);
    }

    // ---- warp-inclusive scan of (a,b) via shuffles ----
    float ia = a, ib = b;
#pragma unroll
    for (int d = 1; d < 32; d <<= 1) {
        float pa = __shfl_up_sync(mask, ia, d);
        float pb = __shfl_up_sync(mask, ib, d);
        if (lane >= d) {
            ib = fmaf(ia, pb, ib);   // compose: prev then cur
            ia = ia * pa;
        }
    }
    // exclusive within warp
    float ea = __shfl_up_sync(mask, ia, 1);
    float eb = __shfl_up_sync(mask, ib, 1);
    if (lane == 0) { ea = 1.0f; eb = 0.0f; }

    // ---- publish warp aggregates; ONE barrier ----
    if (lane == 31) { wa[wid] = ia; wb[wid] = ib; }
    __syncthreads();

    // ---- redundant per-thread exclusive scan over warp aggregates ----
    // (broadcast LDS; no second barrier, no serialized thread-0 scan)
    float pb = 0.0f;
#pragma unroll
    for (int w = 0; w < NWARPS - 1; w++) {
        if (w < wid) {
            pb = fmaf(wa[w], pb, wb[w]);
        }
    }

    // h entering this thread's segment (h_{-1} = 0 => warp-start h = pb)
    float h = fmaf(ea, pb, eb);

    // ---- replay local recurrence with true prefix ----
#pragma unroll
    for (int k = 0; k < EPT; k++) {
        h = fmaf(fv[k], h, xv[k]);
        xv[k] = h;
    }

    // ---- vectorized streaming stores ----
    __stcs((float4*)(out + off),     make_float4(xv[0], xv[1], xv[2], xv[3]));
    __stcs((float4*)(out + off + 4), make_float4(xv[4], xv[5], xv[6], xv[7]));
}

extern "C" void kernel_launch(void* const* d_in, const int* in_sizes, int n_in,
                              void* d_out, int out_size)
{
    const float* f  = (const float*)d_in[0];
    const float* z  = (const float*)d_in[1];
    const float* ii = (const float*)d_in[2];
    float* out = (float*)d_out;

    const int rows = out_size / SEQ_LEN;   // B*H = 16384
    ifo_scan_kernel<<<rows, TPB>>>(f, z, ii, out);
}